// round 11
// baseline (speedup 1.0000x reference)
#include <cuda_runtime.h>
#include <cuda_fp16.h>
#include <cstdint>

#define SS 2048
#define DD 64
#define NBH 32
#define QT 32
#define KCH 64
#define NCH 32
#define C_EXP 0.18033688011112042f      // 0.125 * log2(e)

#define CTX_ELEMS (2LL*16*2048*64)
#define PROB_ELEMS (2LL*16*2048*2048)

__device__ __half g_kh[NBH*SS*DD];
__device__ __half g_vh[NBH*SS*DD];

__global__ void prep_split_kernel(const float* __restrict__ K,
                                  const float* __restrict__ V)
{
    int i = blockIdx.x * 256 + threadIdx.x;
    g_kh[i] = __float2half_rn(K[i]);
    g_vh[i] = __float2half_rn(V[i]);
}

// ---------------- smem: per-warp private staging ------------------------------
// warp w owns [w*9216, (w+1)*9216): pass A = 4 K-slices of 2304B (ring, depth 3)
//                                   pass B = 2 stages of [K 2304 | V 2304]
#define SLICE_B 2304
#define WARP_B  9216
#define OFF_RSUM 73728
#define OFF_LG2  73856
#define SMEM_BYTES 73984

__device__ __forceinline__ uint32_t sptr(const void* p) {
    return (uint32_t)__cvta_generic_to_shared(p);
}
__device__ __forceinline__ void ldmA(uint32_t* a, uint32_t addr) {
    asm volatile("ldmatrix.sync.aligned.m8n8.x4.shared.b16 {%0,%1,%2,%3}, [%4];"
                 : "=r"(a[0]), "=r"(a[1]), "=r"(a[2]), "=r"(a[3]) : "r"(addr));
}
__device__ __forceinline__ void ldmB4(uint32_t* b, uint32_t addr) {
    asm volatile("ldmatrix.sync.aligned.m8n8.x4.shared.b16 {%0,%1,%2,%3}, [%4];"
                 : "=r"(b[0]), "=r"(b[1]), "=r"(b[2]), "=r"(b[3]) : "r"(addr));
}
__device__ __forceinline__ void ldmBT4(uint32_t* b, uint32_t addr) {
    asm volatile("ldmatrix.sync.aligned.m8n8.x4.trans.shared.b16 {%0,%1,%2,%3}, [%4];"
                 : "=r"(b[0]), "=r"(b[1]), "=r"(b[2]), "=r"(b[3]) : "r"(addr));
}
__device__ __forceinline__ void mma16816(float* c, const uint32_t* a, const uint32_t* b) {
    asm volatile("mma.sync.aligned.m16n8k16.row.col.f32.f16.f16.f32 "
                 "{%0,%1,%2,%3}, {%4,%5,%6,%7}, {%8,%9}, {%0,%1,%2,%3};"
                 : "+f"(c[0]), "+f"(c[1]), "+f"(c[2]), "+f"(c[3])
                 : "r"(a[0]), "r"(a[1]), "r"(a[2]), "r"(a[3]), "r"(b[0]), "r"(b[1]));
}
__device__ __forceinline__ void cpa16(uint32_t dst, const void* src) {
    asm volatile("cp.async.cg.shared.global [%0], [%1], 16;" :: "r"(dst), "l"(src));
}
__device__ __forceinline__ void cpa_commit() {
    asm volatile("cp.async.commit_group;");
}
template<int N> __device__ __forceinline__ void cpa_wait() {
    asm volatile("cp.async.wait_group %0;" :: "n"(N));
}
__device__ __forceinline__ float ex2f(float x) {
    float y; asm("ex2.approx.f32 %0, %1;" : "=f"(y) : "f"(x)); return y;
}
__device__ __forceinline__ uint32_t packh2(float a, float b) {
    __half2 t = __floats2half2_rn(a, b);
    return *(uint32_t*)&t;
}
__device__ __forceinline__ void stcs2(float* p, float a, float b) {
    asm volatile("st.global.cs.v2.f32 [%0], {%1,%2};" :: "l"(p), "f"(a), "f"(b));
}

__global__ __launch_bounds__(256, 3)
void sdpa_kernel(const float* __restrict__ Qg_,
                 const int*   __restrict__ Mg_,
                 float* __restrict__ ctx_out,
                 float* __restrict__ prob_out)
{
    extern __shared__ char smem[];
    float* rsum_s = (float*)(smem + OFF_RSUM);
    float* lg2_s  = (float*)(smem + OFF_LG2);

    const int tid = threadIdx.x;
    const int w = tid >> 5, l = tid & 31;
    const int bh = blockIdx.x >> 6;
    const int qt = blockIdx.x & 63;
    const int q0 = qt * QT;
    const int b  = bh >> 4;
    const int mh = w & 1;               // m-half: rows 16*mh..
    const int ns = w >> 1;              // key-slice 16*ns.. (0..3)
    const int lr = l >> 2;
    const int lc = (l & 3) * 2;
    const int r0 = 16 * mh + lr;

    const float* Qg = Qg_ + ((size_t)bh * SS + q0) * DD;
    const int*   mg = Mg_ + (size_t)b * SS;

    // ---- Q load via (temporarily borrowed) staging smem; rowsum init ----
    __half* qtmp = (__half*)smem;
    for (int i = tid; i < QT * DD; i += 256) {
        int r = i >> 6, d = i & 63;
        qtmp[r * 72 + d] = __float2half_rn(Qg[i]);
    }
    if (tid < 32) rsum_s[tid] = 0.f;
    __syncthreads();

    uint32_t qh[16];
    {
        uint32_t qb = sptr(qtmp) + (16 * mh + (l & 15)) * 144 + (l >> 4) * 16;
#pragma unroll
        for (int kt = 0; kt < 4; kt++) ldmA(qh + 4 * kt, qb + kt * 32);
    }
    __syncthreads();                    // Q consumed; staging area free

    // per-warp staging bases / sources
    const __half* gK = g_kh + ((size_t)bh * SS + 16 * ns) * DD;
    const __half* gV = g_vh + ((size_t)bh * SS + 16 * ns) * DD;
    const uint32_t wbase = sptr(smem) + w * WARP_B;
    const int  lrow = l & 15;
    const bool isK = (l < 16);

    // local-row fragment offsets
    const uint32_t kOff4 = (8 * (l >> 4) + (l & 7)) * 144 + ((l >> 3) & 1) * 16;
    const uint32_t vOff4 = (l & 15) * 144 + (l >> 4) * 16;

    // =================== PASS A: row sums (K only, depth-3 ring) ============
    auto issueA = [&](int ch) {
        if (isK) {
            const __half* src = gK + (size_t)(ch * KCH + lrow) * DD;
            uint32_t dst = wbase + (ch & 3) * SLICE_B + lrow * 144;
#pragma unroll
            for (int s8 = 0; s8 < 8; s8++) cpa16(dst + s8 * 16, src + s8 * 8);
        }
        cpa_commit();
    };
    issueA(0); issueA(1); issueA(2);

    float rs0 = 0.f, rs1 = 0.f;
#pragma unroll 1
    for (int ch = 0; ch < NCH; ch++) {
        if (ch < NCH - 2)       cpa_wait<2>();
        else if (ch == NCH - 2) cpa_wait<1>();
        else                    cpa_wait<0>();
        __syncwarp();
        uint32_t kb_s = wbase + (ch & 3) * SLICE_B;
        float acc[2][4] = {};
        uint32_t bq[4];
#pragma unroll
        for (int kt = 0; kt < 4; kt++) {
            ldmB4(bq, kb_s + kOff4 + kt * 32);
            mma16816(acc[0], qh + 4 * kt, bq);
            mma16816(acc[1], qh + 4 * kt, bq + 2);
        }
        int kb = ch * KCH + 16 * ns + lc;
#pragma unroll
        for (int t = 0; t < 2; t++) {
            int2 mm = *(const int2*)(mg + kb + 8 * t);
            rs0 += (mm.x ? 0.f : ex2f(acc[t][0] * C_EXP))
                 + (mm.y ? 0.f : ex2f(acc[t][1] * C_EXP));
            rs1 += (mm.x ? 0.f : ex2f(acc[t][2] * C_EXP))
                 + (mm.y ? 0.f : ex2f(acc[t][3] * C_EXP));
        }
        if (ch + 3 < NCH) issueA(ch + 3);
    }

    // ---- rowsum reduce -> -log2(rsum) ----
    rs0 += __shfl_xor_sync(0xffffffffu, rs0, 1);
    rs0 += __shfl_xor_sync(0xffffffffu, rs0, 2);
    rs1 += __shfl_xor_sync(0xffffffffu, rs1, 1);
    rs1 += __shfl_xor_sync(0xffffffffu, rs1, 2);
    if ((l & 3) == 0) {
        atomicAdd(&rsum_s[r0], rs0);
        atomicAdd(&rsum_s[r0 + 8], rs1);
    }
    __syncthreads();
    if (tid < 32) lg2_s[tid] = -__log2f(rsum_s[tid]);
    __syncthreads();
    const float lg0 = lg2_s[r0], lg1 = lg2_s[r0 + 8];

    // =================== PASS B: normalized probs + PV (depth-2) ============
    auto issueB = [&](int ch) {
        const __half* src = (isK ? gK : gV) + (size_t)(ch * KCH + lrow) * DD;
        uint32_t dst = wbase + (ch & 1) * 2 * SLICE_B + (isK ? 0 : SLICE_B)
                     + lrow * 144;
#pragma unroll
        for (int s8 = 0; s8 < 8; s8++) cpa16(dst + s8 * 16, src + s8 * 8);
        cpa_commit();
    };
    issueB(0); issueB(1);

    float pv[8][4] = {};
    float* probRow = prob_out ? prob_out + ((size_t)bh * SS + q0 + r0) * SS : nullptr;

#pragma unroll 1
    for (int ch = 0; ch < NCH; ch++) {
        if (ch < NCH - 1) cpa_wait<1>();
        else              cpa_wait<0>();
        __syncwarp();
        uint32_t base = wbase + (ch & 1) * 2 * SLICE_B;

        // QK^T
        float acc[2][4] = {};
        uint32_t bq[4];
#pragma unroll
        for (int kt = 0; kt < 4; kt++) {
            ldmB4(bq, base + kOff4 + kt * 32);
            mma16816(acc[0], qh + 4 * kt, bq);
            mma16816(acc[1], qh + 4 * kt, bq + 2);
        }

        // epilogue: normalized exp (folded), prob write, pack P
        int kb = ch * KCH + 16 * ns + lc;
        uint32_t pah[4];
#pragma unroll
        for (int t = 0; t < 2; t++) {
            int2 mm = *(const int2*)(mg + kb + 8 * t);
            float p0 = mm.x ? 0.f : ex2f(acc[t][0] * C_EXP + lg0);
            float p1 = mm.y ? 0.f : ex2f(acc[t][1] * C_EXP + lg0);
            float p2 = mm.x ? 0.f : ex2f(acc[t][2] * C_EXP + lg1);
            float p3 = mm.y ? 0.f : ex2f(acc[t][3] * C_EXP + lg1);
            if (probRow) {
                stcs2(probRow + kb + 8 * t, p0, p1);
                stcs2(probRow + 8 * SS + kb + 8 * t, p2, p3);
            }
            pah[2 * t]     = packh2(p0, p1);
            pah[2 * t + 1] = packh2(p2, p3);
        }

        // PV (normalized P)
        uint32_t vb = base + SLICE_B + vOff4;
        uint32_t bv[4];
#pragma unroll
        for (int jj = 0; jj < 4; jj++) {
            ldmBT4(bv, vb + jj * 32);
            mma16816(pv[2 * jj],     pah, bv);
            mma16816(pv[2 * jj + 1], pah, bv + 2);
        }

        if (ch + 2 < NCH) issueB(ch + 2);
    }

    // =================== cross-warp PV reduction + ctx ======================
    __syncthreads();                    // all warps done with staging
    float* part = (float*)smem;         // 96 rows x 66 floats = 25344B
    if (ns > 0) {
        int pr = (ns - 1) * 32 + 16 * mh + lr;
#pragma unroll
        for (int j = 0; j < 8; j++) {
            *(float2*)(part + pr * 66 + 8 * j + lc)       = make_float2(pv[j][0], pv[j][1]);
            *(float2*)(part + (pr + 8) * 66 + 8 * j + lc) = make_float2(pv[j][2], pv[j][3]);
        }
    }
    __syncthreads();

    if (ns == 0 && ctx_out) {
#pragma unroll
        for (int j = 0; j < 8; j++) {
#pragma unroll
            for (int s = 0; s < 3; s++) {
                int pr = s * 32 + 16 * mh + lr;
                float2 u  = *(float2*)(part + pr * 66 + 8 * j + lc);
                float2 u2 = *(float2*)(part + (pr + 8) * 66 + 8 * j + lc);
                pv[j][0] += u.x;  pv[j][1] += u.y;
                pv[j][2] += u2.x; pv[j][3] += u2.y;
            }
        }
        float* c0 = ctx_out + ((size_t)bh * SS + q0 + r0) * DD;
#pragma unroll
        for (int j = 0; j < 8; j++) {
            *(float2*)(c0 + 8 * j + lc)          = make_float2(pv[j][0], pv[j][1]);
            *(float2*)(c0 + 8 * DD + 8 * j + lc) = make_float2(pv[j][2], pv[j][3]);
        }
    }
}

extern "C" void kernel_launch(void* const* d_in, const int* in_sizes, int n_in,
                              void* d_out, int out_size)
{
    const float* Q = (const float*)d_in[0];
    const float* K = (const float*)d_in[1];
    const float* V = (const float*)d_in[2];
    const int*   M = (const int*)d_in[3];

    float* ctx = nullptr;
    float* prob = nullptr;
    long long os = out_size;
    if (os >= (long long)(CTX_ELEMS + PROB_ELEMS)) {
        ctx  = (float*)d_out;
        prob = (float*)d_out + CTX_ELEMS;
    } else if (os == (long long)PROB_ELEMS) {
        prob = (float*)d_out;
    } else {
        ctx  = (float*)d_out;
    }

    static bool attr_set = false;
    if (!attr_set) {
        cudaFuncSetAttribute(sdpa_kernel,
                             cudaFuncAttributeMaxDynamicSharedMemorySize, SMEM_BYTES);
        attr_set = true;
    }

    prep_split_kernel<<<(NBH * SS * DD) / 256, 256>>>(K, V);
    sdpa_kernel<<<NBH * (SS / QT), 256, SMEM_BYTES>>>(Q, M, ctx, prob);
}

// round 13
// speedup vs baseline: 1.9066x; 1.9066x over previous
#include <cuda_runtime.h>
#include <cuda_fp16.h>
#include <cstdint>

#define SS 2048
#define DD 64
#define NBH 32
#define QT 32
#define KCH 64
#define NCH 32
#define C_EXP 0.18033688011112042f      // 0.125 * log2(e)

#define CTX_ELEMS (2LL*16*2048*64)
#define PROB_ELEMS (2LL*16*2048*2048)

__device__ __half g_kh[NBH*SS*DD];
__device__ __half g_vh[NBH*SS*DD];

__global__ void prep_split_kernel(const float* __restrict__ K,
                                  const float* __restrict__ V)
{
    int i = blockIdx.x * 256 + threadIdx.x;
    g_kh[i] = __float2half_rn(K[i]);
    g_vh[i] = __float2half_rn(V[i]);
}

// ---------------- smem: per-PAIR staging --------------------------------------
// pair ns (warps 2ns,2ns+1) owns 3 stages of [K slice 2304 | V slice 2304]
#define SLICE_B 2304                    // 16 rows x 144B
#define STAGE_B 4608
#define PAIR_B  13824                   // 3 stages
#define OFF_RSUM 55296                  // 4 pairs x 13824
#define OFF_RINV 55424
#define SMEM_BYTES 55552

__device__ __forceinline__ uint32_t sptr(const void* p) {
    return (uint32_t)__cvta_generic_to_shared(p);
}
__device__ __forceinline__ void ldmA(uint32_t* a, uint32_t addr) {
    asm volatile("ldmatrix.sync.aligned.m8n8.x4.shared.b16 {%0,%1,%2,%3}, [%4];"
                 : "=r"(a[0]), "=r"(a[1]), "=r"(a[2]), "=r"(a[3]) : "r"(addr));
}
__device__ __forceinline__ void ldmB4(uint32_t* b, uint32_t addr) {
    asm volatile("ldmatrix.sync.aligned.m8n8.x4.shared.b16 {%0,%1,%2,%3}, [%4];"
                 : "=r"(b[0]), "=r"(b[1]), "=r"(b[2]), "=r"(b[3]) : "r"(addr));
}
__device__ __forceinline__ void ldmBT4(uint32_t* b, uint32_t addr) {
    asm volatile("ldmatrix.sync.aligned.m8n8.x4.trans.shared.b16 {%0,%1,%2,%3}, [%4];"
                 : "=r"(b[0]), "=r"(b[1]), "=r"(b[2]), "=r"(b[3]) : "r"(addr));
}
__device__ __forceinline__ void mma16816(float* c, const uint32_t* a, const uint32_t* b) {
    asm volatile("mma.sync.aligned.m16n8k16.row.col.f32.f16.f16.f32 "
                 "{%0,%1,%2,%3}, {%4,%5,%6,%7}, {%8,%9}, {%0,%1,%2,%3};"
                 : "+f"(c[0]), "+f"(c[1]), "+f"(c[2]), "+f"(c[3])
                 : "r"(a[0]), "r"(a[1]), "r"(a[2]), "r"(a[3]), "r"(b[0]), "r"(b[1]));
}
__device__ __forceinline__ void cpa16(uint32_t dst, const void* src) {
    asm volatile("cp.async.cg.shared.global [%0], [%1], 16;" :: "r"(dst), "l"(src));
}
__device__ __forceinline__ void cpa_commit() {
    asm volatile("cp.async.commit_group;");
}
template<int N> __device__ __forceinline__ void cpa_wait() {
    asm volatile("cp.async.wait_group %0;" :: "n"(N));
}
__device__ __forceinline__ float ex2f(float x) {
    float y; asm("ex2.approx.f32 %0, %1;" : "=f"(y) : "f"(x)); return y;
}
__device__ __forceinline__ uint32_t packh2(float a, float b) {
    __half2 t = __floats2half2_rn(a, b);
    return *(uint32_t*)&t;
}

__global__ __launch_bounds__(256, 3)
void sdpa_kernel(const float* __restrict__ Qg_,
                 const int*   __restrict__ Mg_,
                 float* __restrict__ ctx_out,
                 float* __restrict__ prob_out)
{
    extern __shared__ char smem[];
    float* rsum_s = (float*)(smem + OFF_RSUM);
    float* rinv_s = (float*)(smem + OFF_RINV);

    const int tid = threadIdx.x;
    const int w = tid >> 5, l = tid & 31;
    const int bh = blockIdx.x >> 6;
    const int qt = blockIdx.x & 63;
    const int q0 = qt * QT;
    const int b  = bh >> 4;
    const int mh = w & 1;               // m-half: rows 16*mh.. ; also loader role
    const int ns = w >> 1;              // key-slice 16*ns.. (pair id)
    const int lr = l >> 2;
    const int lc = (l & 3) * 2;
    const int r0 = 16 * mh + lr;

    const float* Qg = Qg_ + ((size_t)bh * SS + q0) * DD;
    const int*   mg = Mg_ + (size_t)b * SS;

    // ---- Q load via borrowed staging smem; rowsum init ----
    __half* qtmp = (__half*)smem;
    for (int i = tid; i < QT * DD; i += 256) {
        int r = i >> 6, d = i & 63;
        qtmp[r * 72 + d] = __float2half_rn(Qg[i]);
    }
    if (tid < 32) rsum_s[tid] = 0.f;
    __syncthreads();

    uint32_t qh[16];
    {
        uint32_t qb = sptr(qtmp) + (16 * mh + (l & 15)) * 144 + (l >> 4) * 16;
#pragma unroll
        for (int kt = 0; kt < 4; kt++) ldmA(qh + 4 * kt, qb + kt * 32);
    }
    __syncthreads();                    // Q consumed; staging free

    // ---- pair staging: mh=0 warp loads K slice, mh=1 warp loads V slice ----
    const __half* gSrc = (mh ? g_vh : g_kh) + ((size_t)bh * SS + 16 * ns) * DD;
    const uint32_t pbase = sptr(smem) + ns * PAIR_B;
    // coalesced: lane l -> row l>>3, seg l&7 (32 lanes = 4 rows = 512B contiguous)
    const uint32_t dOff = (l >> 3) * 144 + (l & 7) * 16 + (mh ? SLICE_B : 0);
    const int      sOff = (l >> 3) * DD + (l & 7) * 8;

    auto issue = [&](int ch) {
        uint32_t dst = pbase + (ch % 3) * STAGE_B + dOff;
        const __half* src = gSrc + (size_t)ch * KCH * DD + sOff;
#pragma unroll
        for (int i = 0; i < 4; i++) cpa16(dst + i * 576, src + i * 256);
        cpa_commit();
    };
    issue(0); issue(1);

    const uint32_t kOff4 = (8 * (l >> 4) + (l & 7)) * 144 + ((l >> 3) & 1) * 16;
    const uint32_t vOff4 = (l & 15) * 144 + (l >> 4) * 16 + SLICE_B;
    float* probRow = prob_out ? prob_out + ((size_t)bh * SS + q0 + r0) * SS : nullptr;

    float pv[8][4] = {};
    float rs0 = 0.f, rs1 = 0.f;

#pragma unroll 1
    for (int ch = 0; ch < NCH; ch++) {
        if (ch < NCH - 1) cpa_wait<1>();
        else              cpa_wait<0>();
        asm volatile("bar.sync %0, 64;" :: "r"(1 + ns) : "memory");
        if (ch + 2 < NCH) issue(ch + 2);      // overwrites stage of ch-1 (pair done)

        const uint32_t base = pbase + (ch % 3) * STAGE_B;

        // ---- QK^T: rows 16mh..+15, keys 16ns..+15 ----
        float acc[2][4] = {};
        uint32_t bq[4];
#pragma unroll
        for (int kt = 0; kt < 4; kt++) {
            ldmB4(bq, base + kOff4 + kt * 32);
            mma16816(acc[0], qh + 4 * kt, bq);
            mma16816(acc[1], qh + 4 * kt, bq + 2);
        }

        // ---- exp + mask + pack (stores deferred past PV) ----
        const int kb = ch * KCH + 16 * ns + lc;
        float p[8];
        uint32_t pah[4];
#pragma unroll
        for (int t = 0; t < 2; t++) {
            int2 mm = *(const int2*)(mg + kb + 8 * t);
            p[4*t+0] = mm.x ? 0.f : ex2f(acc[t][0] * C_EXP);
            p[4*t+1] = mm.y ? 0.f : ex2f(acc[t][1] * C_EXP);
            p[4*t+2] = mm.x ? 0.f : ex2f(acc[t][2] * C_EXP);
            p[4*t+3] = mm.y ? 0.f : ex2f(acc[t][3] * C_EXP);
            rs0 += p[4*t+0] + p[4*t+1];
            rs1 += p[4*t+2] + p[4*t+3];
            pah[2*t]     = packh2(p[4*t+0], p[4*t+1]);
            pah[2*t+1]   = packh2(p[4*t+2], p[4*t+3]);
        }

        // ---- PV first (critical path) ----
        uint32_t bv[4];
#pragma unroll
        for (int jj = 0; jj < 4; jj++) {
            ldmBT4(bv, base + vOff4 + jj * 32);
            mma16816(pv[2 * jj],     pah, bv);
            mma16816(pv[2 * jj + 1], pah, bv + 2);
        }

        // ---- prob stores (unnormalized, writeback for L2 residency) ----
        if (probRow) {
#pragma unroll
            for (int t = 0; t < 2; t++) {
                *(float2*)(probRow + kb + 8 * t)          = make_float2(p[4*t+0], p[4*t+1]);
                *(float2*)(probRow + 8 * SS + kb + 8 * t) = make_float2(p[4*t+2], p[4*t+3]);
            }
        }
    }

    // ---- rowsum reduce ----
    rs0 += __shfl_xor_sync(0xffffffffu, rs0, 1);
    rs0 += __shfl_xor_sync(0xffffffffu, rs0, 2);
    rs1 += __shfl_xor_sync(0xffffffffu, rs1, 1);
    rs1 += __shfl_xor_sync(0xffffffffu, rs1, 2);
    if ((l & 3) == 0) {
        atomicAdd(&rsum_s[r0], rs0);
        atomicAdd(&rsum_s[r0 + 8], rs1);
    }
    __syncthreads();                    // all warps done with staging + atomics

    if (tid < 32) rinv_s[tid] = 1.0f / rsum_s[tid];

    // ---- cross-warp PV reduction (reuse staging smem) ----
    float* part = (float*)smem;         // 96 rows x 66 floats = 25344B
    if (ns > 0) {
        int pr = (ns - 1) * 32 + 16 * mh + lr;
#pragma unroll
        for (int j = 0; j < 8; j++) {
            *(float2*)(part + pr * 66 + 8 * j + lc)       = make_float2(pv[j][0], pv[j][1]);
            *(float2*)(part + (pr + 8) * 66 + 8 * j + lc) = make_float2(pv[j][2], pv[j][3]);
        }
    }
    __syncthreads();

    if (ns == 0 && ctx_out) {
#pragma unroll
        for (int j = 0; j < 8; j++) {
#pragma unroll
            for (int s = 0; s < 3; s++) {
                int pr = s * 32 + 16 * mh + lr;
                float2 u  = *(float2*)(part + pr * 66 + 8 * j + lc);
                float2 u2 = *(float2*)(part + (pr + 8) * 66 + 8 * j + lc);
                pv[j][0] += u.x;  pv[j][1] += u.y;
                pv[j][2] += u2.x; pv[j][3] += u2.y;
            }
        }
        float i0 = rinv_s[r0], i1 = rinv_s[r0 + 8];
        float* c0 = ctx_out + ((size_t)bh * SS + q0 + r0) * DD;
#pragma unroll
        for (int j = 0; j < 8; j++) {
            *(float2*)(c0 + 8 * j + lc) =
                make_float2(pv[j][0] * i0, pv[j][1] * i0);
            *(float2*)(c0 + 8 * DD + 8 * j + lc) =
                make_float2(pv[j][2] * i1, pv[j][3] * i1);
        }
    }

    // ---- tail: normalize this block's prob rows ----
    if (prob_out) {
        float* pbaseg = prob_out + ((size_t)bh * SS + q0) * SS;
#pragma unroll 4
        for (int i = tid; i < QT * (SS / 4); i += 256) {
            int row = i >> 9;
            int c = (i & 511) * 4;
            float inv = rinv_s[row];
            float4 v = *(float4*)(pbaseg + (size_t)row * SS + c);
            v.x *= inv; v.y *= inv; v.z *= inv; v.w *= inv;
            *(float4*)(pbaseg + (size_t)row * SS + c) = v;
        }
    }
}

extern "C" void kernel_launch(void* const* d_in, const int* in_sizes, int n_in,
                              void* d_out, int out_size)
{
    const float* Q = (const float*)d_in[0];
    const float* K = (const float*)d_in[1];
    const float* V = (const float*)d_in[2];
    const int*   M = (const int*)d_in[3];

    float* ctx = nullptr;
    float* prob = nullptr;
    long long os = out_size;
    if (os >= (long long)(CTX_ELEMS + PROB_ELEMS)) {
        ctx  = (float*)d_out;
        prob = (float*)d_out + CTX_ELEMS;
    } else if (os == (long long)PROB_ELEMS) {
        prob = (float*)d_out;
    } else {
        ctx  = (float*)d_out;
    }

    static bool attr_set = false;
    if (!attr_set) {
        cudaFuncSetAttribute(sdpa_kernel,
                             cudaFuncAttributeMaxDynamicSharedMemorySize, SMEM_BYTES);
        attr_set = true;
    }

    prep_split_kernel<<<(NBH * SS * DD) / 256, 256>>>(K, V);
    sdpa_kernel<<<NBH * (SS / QT), 256, SMEM_BYTES>>>(Q, M, ctx, prob);
}